// round 14
// baseline (speedup 1.0000x reference)
#include <cuda_runtime.h>
#include <cuda_bf16.h>
#include <math.h>
#include <stdint.h>

#define TT    2048
#define HD    2048
#define ID    1408
#define ED    16
#define ISD   2816
#define CAPN  1024

// ---- scratch: routing ----
__device__ int   g_counts[ED];
__device__ int   g_slot_tok[ED * CAPN];
__device__ float g_slot_w[ED * CAPN];
// ---- scratch: fp32 u buffers ----
__device__ float g_u_shared[(size_t)TT * ISD];
__device__ float g_u_routed[(size_t)ED * CAPN * ID];
// ---- precast bf16 hi/lo operands ----
__device__ __align__(16) __nv_bfloat16 g_x_hi[(size_t)TT * HD];
__device__ __align__(16) __nv_bfloat16 g_x_lo[(size_t)TT * HD];
__device__ __align__(16) __nv_bfloat16 g_wg_hi[(size_t)ED * HD * ID];
__device__ __align__(16) __nv_bfloat16 g_wg_lo[(size_t)ED * HD * ID];
__device__ __align__(16) __nv_bfloat16 g_wu_hi[(size_t)ED * HD * ID];
__device__ __align__(16) __nv_bfloat16 g_wu_lo[(size_t)ED * HD * ID];
__device__ __align__(16) __nv_bfloat16 g_wd_hi[(size_t)ED * ID * HD];
__device__ __align__(16) __nv_bfloat16 g_wd_lo[(size_t)ED * ID * HD];
__device__ __align__(16) __nv_bfloat16 g_wsg_hi[(size_t)HD * ISD];
__device__ __align__(16) __nv_bfloat16 g_wsg_lo[(size_t)HD * ISD];
__device__ __align__(16) __nv_bfloat16 g_wsu_hi[(size_t)HD * ISD];
__device__ __align__(16) __nv_bfloat16 g_wsu_lo[(size_t)HD * ISD];
__device__ __align__(16) __nv_bfloat16 g_wsd_hi[(size_t)ISD * HD];
__device__ __align__(16) __nv_bfloat16 g_wsd_lo[(size_t)ISD * HD];
__device__ __align__(16) __nv_bfloat16 g_hsh_hi[(size_t)TT * ISD];
__device__ __align__(16) __nv_bfloat16 g_hsh_lo[(size_t)TT * ISD];
__device__ __align__(16) __nv_bfloat16 g_hrt_hi[(size_t)ED * CAPN * ID];
__device__ __align__(16) __nv_bfloat16 g_hrt_lo[(size_t)ED * CAPN * ID];

// ---- SMEM geometry (bytes) ----
#define ASTRIDE_B 80
#define BSTRIDE_B 272
#define AHI 0
#define ALO 10240
#define BHI 20480
#define BLO 29184
#define STAGE 37888
#define NSTAGE 4
#define DSMEM (NSTAGE * STAGE)

__device__ __forceinline__ uint32_t smem_u32(const void* p) {
    uint32_t a;
    asm("{ .reg .u64 t; cvta.to.shared.u64 t, %1; cvt.u32.u64 %0, t; }" : "=r"(a) : "l"(p));
    return a;
}
__device__ __forceinline__ void cpa16(uint32_t dst, const void* src) {
    size_t g = __cvta_generic_to_global(src);
    asm volatile("cp.async.cg.shared.global [%0], [%1], 16;" :: "r"(dst), "l"(g) : "memory");
}
#define CP_COMMIT() asm volatile("cp.async.commit_group;" ::: "memory")
#define CP_WAIT2()  asm volatile("cp.async.wait_group 2;" ::: "memory")

#define LDSM_X4(r, a) \
    asm volatile("ldmatrix.sync.aligned.m8n8.x4.shared.b16 {%0,%1,%2,%3}, [%4];" \
        : "=r"((r)[0]), "=r"((r)[1]), "=r"((r)[2]), "=r"((r)[3]) : "r"(a))
#define LDSM_X4T(r0, r1, r2, r3, a) \
    asm volatile("ldmatrix.sync.aligned.m8n8.x4.trans.shared.b16 {%0,%1,%2,%3}, [%4];" \
        : "=r"(r0), "=r"(r1), "=r"(r2), "=r"(r3) : "r"(a))
#define MMA_BF16(d, a, b0, b1) \
    asm volatile("mma.sync.aligned.m16n8k16.row.col.f32.bf16.bf16.f32 " \
        "{%0,%1,%2,%3}, {%4,%5,%6,%7}, {%8,%9}, {%0,%1,%2,%3};" \
        : "+f"((d)[0]), "+f"((d)[1]), "+f"((d)[2]), "+f"((d)[3]) \
        : "r"((a)[0]), "r"((a)[1]), "r"((a)[2]), "r"((a)[3]), "r"(b0), "r"(b1))

// ================= precast: fp32 -> bf16 hi/lo =================
// W: 0=x 1=wg 2=wu 3=wd 4=wsg 5=wsu 6=wsd
template <int W>
__global__ void precast_kernel(const float4* __restrict__ src, int n4) {
    uint2* hi; uint2* lo;
    if      (W == 0) { hi = (uint2*)g_x_hi;   lo = (uint2*)g_x_lo;   }
    else if (W == 1) { hi = (uint2*)g_wg_hi;  lo = (uint2*)g_wg_lo;  }
    else if (W == 2) { hi = (uint2*)g_wu_hi;  lo = (uint2*)g_wu_lo;  }
    else if (W == 3) { hi = (uint2*)g_wd_hi;  lo = (uint2*)g_wd_lo;  }
    else if (W == 4) { hi = (uint2*)g_wsg_hi; lo = (uint2*)g_wsg_lo; }
    else if (W == 5) { hi = (uint2*)g_wsu_hi; lo = (uint2*)g_wsu_lo; }
    else             { hi = (uint2*)g_wsd_hi; lo = (uint2*)g_wsd_lo; }
    for (int i = blockIdx.x * blockDim.x + threadIdx.x; i < n4; i += gridDim.x * blockDim.x) {
        float4 v = src[i];
        __nv_bfloat162 h0 = __floats2bfloat162_rn(v.x, v.y);
        __nv_bfloat162 h1 = __floats2bfloat162_rn(v.z, v.w);
        __nv_bfloat162 l0 = __floats2bfloat162_rn(v.x - __bfloat162float(h0.x),
                                                  v.y - __bfloat162float(h0.y));
        __nv_bfloat162 l1 = __floats2bfloat162_rn(v.z - __bfloat162float(h1.x),
                                                  v.w - __bfloat162float(h1.y));
        hi[i] = make_uint2(*(uint32_t*)&h0, *(uint32_t*)&h1);
        lo[i] = make_uint2(*(uint32_t*)&l0, *(uint32_t*)&l1);
    }
}

// ================= routing =================
__global__ void init_counts_kernel() {
    if (threadIdx.x < ED) g_counts[threadIdx.x] = 0;
}

__global__ void router_kernel(const float* __restrict__ x, const float* __restrict__ gw) {
    int t = blockIdx.x;
    int warp = threadIdx.x >> 5, lane = threadIdx.x & 31;
    const float4* x4 = (const float4*)(x + (size_t)t * HD);
    const float4* w4 = (const float4*)(gw + (size_t)warp * HD);
    float acc = 0.f;
#pragma unroll 4
    for (int i = lane; i < HD / 4; i += 32) {
        float4 a = x4[i], b = w4[i];
        acc += a.x * b.x + a.y * b.y + a.z * b.z + a.w * b.w;
    }
#pragma unroll
    for (int o = 16; o > 0; o >>= 1) acc += __shfl_xor_sync(0xffffffffu, acc, o);
    __shared__ float logits[ED];
    if (lane == 0) logits[warp] = acc;
    __syncthreads();
    if (threadIdx.x == 0) {
        float mx = -1e30f;
        for (int e = 0; e < ED; e++) mx = fmaxf(mx, logits[e]);
        float s = 0.f, ex[ED];
        for (int e = 0; e < ED; e++) { ex[e] = expf(logits[e] - mx); s += ex[e]; }
        int i1 = 0; float v1 = logits[0];
        for (int e = 1; e < ED; e++) if (logits[e] > v1) { v1 = logits[e]; i1 = e; }
        int i2 = -1; float v2 = -1e30f;
        for (int e = 0; e < ED; e++) if (e != i1 && logits[e] > v2) { v2 = logits[e]; i2 = e; }
        float w1 = ex[i1] / s, w2 = ex[i2] / s;
        int s1 = atomicAdd(&g_counts[i1], 1);
        if (s1 < CAPN) { g_slot_tok[i1 * CAPN + s1] = t; g_slot_w[i1 * CAPN + s1] = w1; }
        int s2 = atomicAdd(&g_counts[i2], 1);
        if (s2 < CAPN) { g_slot_tok[i2 * CAPN + s2] = t; g_slot_w[i2 * CAPN + s2] = w2; }
    }
}

// ================= HMMA GEMM, 6 modes, cp.async pipeline =================
// 0 u_sh=x@wsu  1 h_sh=silu(x@wsg)*u_sh (writes bf16 hi/lo)  2 out=h_sh@wsd
// 3 u_rt=gx@wu  4 h_rt=silu(gx@wg)*u_rt (writes bf16 hi/lo)  5 out+=w*(h_rt@wd)
template <int MODE>
__global__ void __launch_bounds__(256)
moe_hmma(float* __restrict__ outArg)
{
    constexpr bool ROUTED = (MODE >= 3);
    constexpr bool GATHER = (MODE == 3 || MODE == 4);
    constexpr int N = (MODE <= 1) ? ISD : (MODE == 2 || MODE == 5) ? HD : ID;
    constexpr int K = (MODE <= 1) ? HD : (MODE == 2) ? ISD : (MODE == 5) ? ID : HD;

    const int e = ROUTED ? blockIdx.z : 0;
    int M;
    if (ROUTED) { M = g_counts[e]; if (M > CAPN) M = CAPN; } else M = TT;
    const int bm = blockIdx.y * 128;
    if (bm >= M) return;
    const int bn = blockIdx.x * 128;

    const int tid = threadIdx.x, lane = tid & 31, warp = tid >> 5;
    const int wm = warp & 3, wn = warp >> 2;

    __shared__ int   s_tok[128];
    __shared__ float s_wt[128];
    extern __shared__ char smem_raw[];
    const uint32_t sb = smem_u32(smem_raw);

    if (ROUTED) {
        if (tid < 128) {
            int r = bm + tid;
            s_tok[tid] = (r < M) ? g_slot_tok[e * CAPN + r] : g_slot_tok[e * CAPN];
            s_wt[tid]  = (r < M) ? g_slot_w[e * CAPN + r]  : 0.f;
        }
        __syncthreads();
    }

    // A/B bf16 hi/lo sources by mode
    const __nv_bfloat16 *Ahi, *Alo, *Bhi, *Blo;
    if (MODE == 0) { Ahi = g_x_hi;  Alo = g_x_lo;  Bhi = g_wsu_hi; Blo = g_wsu_lo; }
    if (MODE == 1) { Ahi = g_x_hi;  Alo = g_x_lo;  Bhi = g_wsg_hi; Blo = g_wsg_lo; }
    if (MODE == 2) { Ahi = g_hsh_hi; Alo = g_hsh_lo; Bhi = g_wsd_hi; Blo = g_wsd_lo; }
    if (MODE == 3) { Ahi = g_x_hi;  Alo = g_x_lo;  Bhi = g_wu_hi + (size_t)e * HD * ID; Blo = g_wu_lo + (size_t)e * HD * ID; }
    if (MODE == 4) { Ahi = g_x_hi;  Alo = g_x_lo;  Bhi = g_wg_hi + (size_t)e * HD * ID; Blo = g_wg_lo + (size_t)e * HD * ID; }
    if (MODE == 5) { Ahi = g_hrt_hi + (size_t)e * CAPN * ID; Alo = g_hrt_lo + (size_t)e * CAPN * ID;
                     Bhi = g_wd_hi + (size_t)e * ID * HD;    Blo = g_wd_lo + (size_t)e * ID * HD; }

    // per-thread load assignments
    const int arow_i = tid >> 1;              // 0..127 (m row)
    const int akc    = (tid & 1) * 2;         // A chunk base (16B chunks)
    size_t arow_off;
    if (GATHER)        arow_off = (size_t)s_tok[arow_i] * HD;
    else               arow_off = (size_t)(bm + arow_i) * K;
    const __nv_bfloat16* a_hi_src = Ahi + arow_off + akc * 8;
    const __nv_bfloat16* a_lo_src = Alo + arow_off + akc * 8;

    const int krow = tid >> 3;                // 0..31 (k row)
    const int bkc  = (tid & 7) * 2;           // B chunk base
    const __nv_bfloat16* b_hi_src = Bhi + (size_t)krow * N + bn + bkc * 8;
    const __nv_bfloat16* b_lo_src = Blo + (size_t)krow * N + bn + bkc * 8;

    const uint32_t a_dst = (uint32_t)(arow_i * ASTRIDE_B + akc * 16);
    const uint32_t b_dst = (uint32_t)(krow * BSTRIDE_B + bkc * 16);
    const uint32_t a_ld  = (uint32_t)((wm * 32 + (lane & 15)) * ASTRIDE_B + (lane >> 4) * 16);
    const uint32_t b_ld  = (uint32_t)((lane & 15) * BSTRIDE_B + (wn * 64 + (lane >> 4) * 8) * 2);

    float acc[2][8][4];
#pragma unroll
    for (int i = 0; i < 2; i++)
#pragma unroll
        for (int j = 0; j < 8; j++)
#pragma unroll
            for (int q = 0; q < 4; q++) acc[i][j][q] = 0.f;

    auto issue = [&](int t) {
        uint32_t base = sb + (uint32_t)(t & (NSTAGE - 1)) * STAGE;
        const __nv_bfloat16* ah = a_hi_src + t * 32;
        const __nv_bfloat16* al = a_lo_src + t * 32;
        cpa16(base + AHI + a_dst,      ah);
        cpa16(base + AHI + a_dst + 16, ah + 8);
        cpa16(base + ALO + a_dst,      al);
        cpa16(base + ALO + a_dst + 16, al + 8);
        const __nv_bfloat16* bh = b_hi_src + (size_t)t * 32 * N;
        const __nv_bfloat16* bl = b_lo_src + (size_t)t * 32 * N;
        cpa16(base + BHI + b_dst,      bh);
        cpa16(base + BHI + b_dst + 16, bh + 8);
        cpa16(base + BLO + b_dst,      bl);
        cpa16(base + BLO + b_dst + 16, bl + 8);
        CP_COMMIT();
    };

    auto compute = [&](int t) {
        uint32_t base = sb + (uint32_t)(t & (NSTAGE - 1)) * STAGE;
#pragma unroll
        for (int kt = 0; kt < 2; kt++) {
            uint32_t a_hi[2][4], a_lo[2][4];
            uint32_t ab = base + AHI + a_ld + kt * 32;
            LDSM_X4(a_hi[0], ab);
            LDSM_X4(a_hi[1], ab + 16 * ASTRIDE_B);
            uint32_t al = base + ALO + a_ld + kt * 32;
            LDSM_X4(a_lo[0], al);
            LDSM_X4(a_lo[1], al + 16 * ASTRIDE_B);
            uint32_t b_hi[8][2], b_lo[8][2];
            uint32_t bb = base + BHI + b_ld + kt * 16 * BSTRIDE_B;
            uint32_t bl = base + BLO + b_ld + kt * 16 * BSTRIDE_B;
#pragma unroll
            for (int nb = 0; nb < 4; nb++) {
                LDSM_X4T(b_hi[2 * nb][0], b_hi[2 * nb][1], b_hi[2 * nb + 1][0], b_hi[2 * nb + 1][1], bb + nb * 32);
                LDSM_X4T(b_lo[2 * nb][0], b_lo[2 * nb][1], b_lo[2 * nb + 1][0], b_lo[2 * nb + 1][1], bl + nb * 32);
            }
#pragma unroll
            for (int mf = 0; mf < 2; mf++)
#pragma unroll
                for (int nf = 0; nf < 8; nf++) {
                    MMA_BF16(acc[mf][nf], a_hi[mf], b_hi[nf][0], b_hi[nf][1]);
                    MMA_BF16(acc[mf][nf], a_hi[mf], b_lo[nf][0], b_lo[nf][1]);
                    MMA_BF16(acc[mf][nf], a_lo[mf], b_hi[nf][0], b_hi[nf][1]);
                }
        }
    };

    const int NT = K / 32;
    issue(0); issue(1); issue(2);
    for (int t = 0; t < NT; t++) {
        CP_WAIT2();
        __syncthreads();
        if (t + 3 < NT) issue(t + 3);
        compute(t);
    }

    // ---- epilogue ----
#pragma unroll
    for (int mf = 0; mf < 2; mf++) {
#pragma unroll
        for (int nf = 0; nf < 8; nf++) {
            int n = bn + wn * 64 + nf * 8 + (lane & 3) * 2;
#pragma unroll
            for (int h = 0; h < 2; h++) {
                int ml = wm * 32 + mf * 16 + (lane >> 2) + h * 8;
                int m  = bm + ml;
                if (m < M) {
                    float d0 = acc[mf][nf][2 * h], d1 = acc[mf][nf][2 * h + 1];
                    if (MODE == 0) {
                        *(float2*)&g_u_shared[(size_t)m * ISD + n] = make_float2(d0, d1);
                    } else if (MODE == 1) {
                        float2 u = *(const float2*)&g_u_shared[(size_t)m * ISD + n];
                        float h0 = d0 / (1.f + expf(-d0)) * u.x;
                        float h1 = d1 / (1.f + expf(-d1)) * u.y;
                        __nv_bfloat162 hh = __floats2bfloat162_rn(h0, h1);
                        __nv_bfloat162 ll = __floats2bfloat162_rn(h0 - __bfloat162float(hh.x),
                                                                  h1 - __bfloat162float(hh.y));
                        *(uint32_t*)&g_hsh_hi[(size_t)m * ISD + n] = *(uint32_t*)&hh;
                        *(uint32_t*)&g_hsh_lo[(size_t)m * ISD + n] = *(uint32_t*)&ll;
                    } else if (MODE == 2) {
                        *(float2*)&outArg[(size_t)m * HD + n] = make_float2(d0, d1);
                    } else if (MODE == 3) {
                        *(float2*)&g_u_routed[((size_t)e * CAPN + m) * ID + n] = make_float2(d0, d1);
                    } else if (MODE == 4) {
                        float2 u = *(const float2*)&g_u_routed[((size_t)e * CAPN + m) * ID + n];
                        float h0 = d0 / (1.f + expf(-d0)) * u.x;
                        float h1 = d1 / (1.f + expf(-d1)) * u.y;
                        __nv_bfloat162 hh = __floats2bfloat162_rn(h0, h1);
                        __nv_bfloat162 ll = __floats2bfloat162_rn(h0 - __bfloat162float(hh.x),
                                                                  h1 - __bfloat162float(hh.y));
                        *(uint32_t*)&g_hrt_hi[((size_t)e * CAPN + m) * ID + n] = *(uint32_t*)&hh;
                        *(uint32_t*)&g_hrt_lo[((size_t)e * CAPN + m) * ID + n] = *(uint32_t*)&ll;
                    } else {
                        int tok = s_tok[ml];
                        float wgt = s_wt[ml];
                        atomicAdd(&outArg[(size_t)tok * HD + n],     wgt * d0);
                        atomicAdd(&outArg[(size_t)tok * HD + n + 1], wgt * d1);
                    }
                }
            }
        }
    }
}

// ================= launch =================
extern "C" void kernel_launch(void* const* d_in, const int* in_sizes, int n_in,
                              void* d_out, int out_size) {
    const float* x       = (const float*)d_in[0];
    const float* gate_w  = (const float*)d_in[1];
    const float* w_gate  = (const float*)d_in[2];
    const float* w_up    = (const float*)d_in[3];
    const float* w_down  = (const float*)d_in[4];
    const float* ws_gate = (const float*)d_in[5];
    const float* ws_up   = (const float*)d_in[6];
    const float* ws_down = (const float*)d_in[7];
    float* out = (float*)d_out;

    cudaFuncSetAttribute(moe_hmma<0>, cudaFuncAttributeMaxDynamicSharedMemorySize, DSMEM);
    cudaFuncSetAttribute(moe_hmma<1>, cudaFuncAttributeMaxDynamicSharedMemorySize, DSMEM);
    cudaFuncSetAttribute(moe_hmma<2>, cudaFuncAttributeMaxDynamicSharedMemorySize, DSMEM);
    cudaFuncSetAttribute(moe_hmma<3>, cudaFuncAttributeMaxDynamicSharedMemorySize, DSMEM);
    cudaFuncSetAttribute(moe_hmma<4>, cudaFuncAttributeMaxDynamicSharedMemorySize, DSMEM);
    cudaFuncSetAttribute(moe_hmma<5>, cudaFuncAttributeMaxDynamicSharedMemorySize, DSMEM);

    init_counts_kernel<<<1, 32>>>();
    router_kernel<<<TT, 512>>>(x, gate_w);

    const int PG = 2048, PB = 256;
    precast_kernel<0><<<PG, PB>>>((const float4*)x,       (int)((size_t)TT * HD / 4));
    precast_kernel<1><<<PG, PB>>>((const float4*)w_gate,  (int)((size_t)ED * HD * ID / 4));
    precast_kernel<2><<<PG, PB>>>((const float4*)w_up,    (int)((size_t)ED * HD * ID / 4));
    precast_kernel<3><<<PG, PB>>>((const float4*)w_down,  (int)((size_t)ED * ID * HD / 4));
    precast_kernel<4><<<PG, PB>>>((const float4*)ws_gate, (int)((size_t)HD * ISD / 4));
    precast_kernel<5><<<PG, PB>>>((const float4*)ws_up,   (int)((size_t)HD * ISD / 4));
    precast_kernel<6><<<PG, PB>>>((const float4*)ws_down, (int)((size_t)ISD * HD / 4));

    moe_hmma<0><<<dim3(ISD / 128, TT / 128), 256, DSMEM>>>(out);
    moe_hmma<1><<<dim3(ISD / 128, TT / 128), 256, DSMEM>>>(out);
    moe_hmma<2><<<dim3(HD / 128, TT / 128), 256, DSMEM>>>(out);

    moe_hmma<3><<<dim3(ID / 128, CAPN / 128, ED), 256, DSMEM>>>(out);
    moe_hmma<4><<<dim3(ID / 128, CAPN / 128, ED), 256, DSMEM>>>(out);
    moe_hmma<5><<<dim3(HD / 128, CAPN / 128, ED), 256, DSMEM>>>(out);
}

// round 15
// speedup vs baseline: 1.3068x; 1.3068x over previous
#include <cuda_runtime.h>
#include <cuda_bf16.h>
#include <math.h>
#include <stdint.h>

#define TT    2048
#define HD    2048
#define ID    1408
#define ED    16
#define ISD   2816
#define CAPN  1024

__device__ int   g_counts[ED];
__device__ int   g_slot_tok[ED * CAPN];
__device__ float g_slot_w[ED * CAPN];
__device__ float g_u_shared[(size_t)TT * ISD];
__device__ float g_h_shared[(size_t)TT * ISD];
__device__ float g_u_routed[(size_t)ED * CAPN * ID];
__device__ float g_h_routed[(size_t)ED * CAPN * ID];

// SMEM geometry (bytes): A tile 64 rows x 32k bf16 (stride 80B), B tile 32k x 64n bf16 (stride 144B)
#define ASTRIDE_B 80
#define BSTRIDE_B 144
#define AHI 0
#define ALO 5120
#define BHI 10240
#define BLO 14848
#define STAGE 19456
#define DSMEM (2 * STAGE)

__device__ __forceinline__ uint32_t smem_u32(const void* p) {
    uint32_t a;
    asm("{ .reg .u64 t; cvta.to.shared.u64 t, %1; cvt.u32.u64 %0, t; }" : "=r"(a) : "l"(p));
    return a;
}
__device__ __forceinline__ void sts128(uint32_t a, uint32_t x, uint32_t y, uint32_t z, uint32_t w) {
    asm volatile("st.shared.v4.b32 [%0], {%1, %2, %3, %4};" :: "r"(a), "r"(x), "r"(y), "r"(z), "r"(w) : "memory");
}
__device__ __forceinline__ void cvt_hilo(float a, float b, uint32_t& h, uint32_t& l) {
    __nv_bfloat162 hh = __floats2bfloat162_rn(a, b);
    __nv_bfloat162 ll = __floats2bfloat162_rn(a - __bfloat162float(hh.x),
                                              b - __bfloat162float(hh.y));
    h = *(uint32_t*)&hh; l = *(uint32_t*)&ll;
}

#define LDSM_X4(r, a) \
    asm volatile("ldmatrix.sync.aligned.m8n8.x4.shared.b16 {%0,%1,%2,%3}, [%4];" \
        : "=r"((r)[0]), "=r"((r)[1]), "=r"((r)[2]), "=r"((r)[3]) : "r"(a))
#define LDSM_X4T(r0, r1, r2, r3, a) \
    asm volatile("ldmatrix.sync.aligned.m8n8.x4.trans.shared.b16 {%0,%1,%2,%3}, [%4];" \
        : "=r"(r0), "=r"(r1), "=r"(r2), "=r"(r3) : "r"(a))
#define MMA_BF16(d, a, b0, b1) \
    asm volatile("mma.sync.aligned.m16n8k16.row.col.f32.bf16.bf16.f32 " \
        "{%0,%1,%2,%3}, {%4,%5,%6,%7}, {%8,%9}, {%0,%1,%2,%3};" \
        : "+f"((d)[0]), "+f"((d)[1]), "+f"((d)[2]), "+f"((d)[3]) \
        : "r"((a)[0]), "r"((a)[1]), "r"((a)[2]), "r"((a)[3]), "r"(b0), "r"(b1))

__global__ void init_counts_kernel() {
    if (threadIdx.x < ED) g_counts[threadIdx.x] = 0;
}

__global__ void router_kernel(const float* __restrict__ x, const float* __restrict__ gw) {
    int t = blockIdx.x;
    int warp = threadIdx.x >> 5, lane = threadIdx.x & 31;
    const float4* x4 = (const float4*)(x + (size_t)t * HD);
    const float4* w4 = (const float4*)(gw + (size_t)warp * HD);
    float acc = 0.f;
#pragma unroll 4
    for (int i = lane; i < HD / 4; i += 32) {
        float4 a = x4[i], b = w4[i];
        acc += a.x * b.x + a.y * b.y + a.z * b.z + a.w * b.w;
    }
#pragma unroll
    for (int o = 16; o > 0; o >>= 1) acc += __shfl_xor_sync(0xffffffffu, acc, o);
    __shared__ float logits[ED];
    if (lane == 0) logits[warp] = acc;
    __syncthreads();
    if (threadIdx.x == 0) {
        float mx = -1e30f;
        for (int e = 0; e < ED; e++) mx = fmaxf(mx, logits[e]);
        float s = 0.f, ex[ED];
        for (int e = 0; e < ED; e++) { ex[e] = expf(logits[e] - mx); s += ex[e]; }
        int i1 = 0; float v1 = logits[0];
        for (int e = 1; e < ED; e++) if (logits[e] > v1) { v1 = logits[e]; i1 = e; }
        int i2 = -1; float v2 = -1e30f;
        for (int e = 0; e < ED; e++) if (e != i1 && logits[e] > v2) { v2 = logits[e]; i2 = e; }
        float w1 = ex[i1] / s, w2 = ex[i2] / s;
        int s1 = atomicAdd(&g_counts[i1], 1);
        if (s1 < CAPN) { g_slot_tok[i1 * CAPN + s1] = t; g_slot_w[i1 * CAPN + s1] = w1; }
        int s2 = atomicAdd(&g_counts[i2], 1);
        if (s2 < CAPN) { g_slot_tok[i2 * CAPN + s2] = t; g_slot_w[i2 * CAPN + s2] = w2; }
    }
}

// modes: 0 u_sh=x@ws_up  1 h_sh=silu(x@ws_gate)*u_sh  2 out=h_sh@ws_down
//        3 u_rt=gx@w_up  4 h_rt=silu(gx@w_gate)*u_rt  5 out+=w*(h_rt@w_down)
// 128 threads, 4 warps, block tile 64m x 64n, warp tile 32m x 32n.
template <int MODE>
__global__ void __launch_bounds__(128, 4)
moe_hmma(const float* __restrict__ Aarg, const float* __restrict__ Barg,
         float* __restrict__ outArg)
{
    constexpr bool ROUTED = (MODE >= 3);
    constexpr bool GATHER = (MODE == 3 || MODE == 4);
    constexpr int N = (MODE <= 1) ? ISD : (MODE == 2 || MODE == 5) ? HD : ID;
    constexpr int K = (MODE <= 1) ? HD : (MODE == 2) ? ISD : (MODE == 5) ? ID : HD;

    const int e = ROUTED ? blockIdx.z : 0;
    int M;
    if (ROUTED) { M = g_counts[e]; if (M > CAPN) M = CAPN; } else M = TT;
    const int bm = blockIdx.y * 64;
    if (bm >= M) return;
    const int bn = blockIdx.x * 64;

    const int tid = threadIdx.x, lane = tid & 31, warp = tid >> 5;
    const int wm = warp & 1, wn = warp >> 1;

    __shared__ int   s_tok[64];
    __shared__ float s_wt[64];
    extern __shared__ char smem_raw[];
    const uint32_t sb = smem_u32(smem_raw);

    if (ROUTED) {
        if (tid < 64) {
            int r = bm + tid;
            s_tok[tid] = (r < M) ? g_slot_tok[e * CAPN + r] : g_slot_tok[e * CAPN];
            s_wt[tid]  = (r < M) ? g_slot_w[e * CAPN + r]  : 0.f;
        }
        __syncthreads();
    }

    const float* Abase;
    if (MODE == 2)      Abase = g_h_shared;
    else if (MODE == 5) Abase = g_h_routed + (size_t)e * CAPN * ID;
    else                Abase = Aarg;
    const float* B = Barg + (ROUTED ? (size_t)e * HD * ID : (size_t)0);

    // A loads: 2 threads/row, 16 floats each (64 rows x 32 k)
    const int arow_i = tid >> 1;
    const int kq     = (tid & 1) * 16;
    const float* arow = GATHER ? Aarg + (size_t)s_tok[arow_i] * HD
                               : Abase + (size_t)(bm + arow_i) * K;
    // B loads: 4 threads/k-row, 16 floats each (32 k x 64 n)
    const int krow = tid >> 2;
    const int nq   = (tid & 3) * 16;
    const float* brow = B + (size_t)krow * N + bn + nq;

    const uint32_t a_sts = (uint32_t)(arow_i * ASTRIDE_B + kq * 2);
    const uint32_t b_sts = (uint32_t)(krow * BSTRIDE_B + nq * 2);
    const uint32_t a_ld  = (uint32_t)((wm * 32 + (lane & 15)) * ASTRIDE_B + (lane >> 4) * 16);
    const uint32_t b_ld  = (uint32_t)((lane & 15) * BSTRIDE_B + (wn * 32 + (lane >> 4) * 8) * 2);

    float acc[2][4][4];
#pragma unroll
    for (int i = 0; i < 2; i++)
#pragma unroll
        for (int j = 0; j < 4; j++)
#pragma unroll
            for (int q = 0; q < 4; q++) acc[i][j][q] = 0.f;

    float4 pa[4], pb[4];
    auto ldg_stage = [&](int t) {
        const float* pA = arow + t * 32 + kq;
#pragma unroll
        for (int i = 0; i < 4; i++) pa[i] = *(const float4*)(pA + 4 * i);
        const float* pB = brow + (size_t)(t * 32) * N;
#pragma unroll
        for (int i = 0; i < 4; i++) pb[i] = *(const float4*)(pB + 4 * i);
    };
    auto cvt_sts = [&](int t) {
        uint32_t base = sb + (uint32_t)(t & 1) * STAGE;
        uint32_t h[8], l[8];
        cvt_hilo(pa[0].x, pa[0].y, h[0], l[0]); cvt_hilo(pa[0].z, pa[0].w, h[1], l[1]);
        cvt_hilo(pa[1].x, pa[1].y, h[2], l[2]); cvt_hilo(pa[1].z, pa[1].w, h[3], l[3]);
        cvt_hilo(pa[2].x, pa[2].y, h[4], l[4]); cvt_hilo(pa[2].z, pa[2].w, h[5], l[5]);
        cvt_hilo(pa[3].x, pa[3].y, h[6], l[6]); cvt_hilo(pa[3].z, pa[3].w, h[7], l[7]);
        sts128(base + AHI + a_sts,      h[0], h[1], h[2], h[3]);
        sts128(base + AHI + a_sts + 16, h[4], h[5], h[6], h[7]);
        sts128(base + ALO + a_sts,      l[0], l[1], l[2], l[3]);
        sts128(base + ALO + a_sts + 16, l[4], l[5], l[6], l[7]);
        cvt_hilo(pb[0].x, pb[0].y, h[0], l[0]); cvt_hilo(pb[0].z, pb[0].w, h[1], l[1]);
        cvt_hilo(pb[1].x, pb[1].y, h[2], l[2]); cvt_hilo(pb[1].z, pb[1].w, h[3], l[3]);
        cvt_hilo(pb[2].x, pb[2].y, h[4], l[4]); cvt_hilo(pb[2].z, pb[2].w, h[5], l[5]);
        cvt_hilo(pb[3].x, pb[3].y, h[6], l[6]); cvt_hilo(pb[3].z, pb[3].w, h[7], l[7]);
        sts128(base + BHI + b_sts,      h[0], h[1], h[2], h[3]);
        sts128(base + BHI + b_sts + 16, h[4], h[5], h[6], h[7]);
        sts128(base + BLO + b_sts,      l[0], l[1], l[2], l[3]);
        sts128(base + BLO + b_sts + 16, l[4], l[5], l[6], l[7]);
    };
    auto compute = [&](int t) {
        uint32_t base = sb + (uint32_t)(t & 1) * STAGE;
#pragma unroll
        for (int kt = 0; kt < 2; kt++) {
            uint32_t a_hi[2][4], a_lo[2][4];
            uint32_t ab = base + AHI + a_ld + kt * 32;
            LDSM_X4(a_hi[0], ab);
            LDSM_X4(a_hi[1], ab + 16 * ASTRIDE_B);
            uint32_t al = base + ALO + a_ld + kt * 32;
            LDSM_X4(a_lo[0], al);
            LDSM_X4(a_lo[1], al + 16 * ASTRIDE_B);
            uint32_t b_hi[4][2], b_lo[4][2];
            uint32_t bb = base + BHI + b_ld + kt * 16 * BSTRIDE_B;
            uint32_t bl = base + BLO + b_ld + kt * 16 * BSTRIDE_B;
#pragma unroll
            for (int nb = 0; nb < 2; nb++) {
                LDSM_X4T(b_hi[2 * nb][0], b_hi[2 * nb][1], b_hi[2 * nb + 1][0], b_hi[2 * nb + 1][1], bb + nb * 32);
                LDSM_X4T(b_lo[2 * nb][0], b_lo[2 * nb][1], b_lo[2 * nb + 1][0], b_lo[2 * nb + 1][1], bl + nb * 32);
            }
#pragma unroll
            for (int mf = 0; mf < 2; mf++)
#pragma unroll
                for (int nf = 0; nf < 4; nf++) {
                    MMA_BF16(acc[mf][nf], a_hi[mf], b_hi[nf][0], b_hi[nf][1]);
                    MMA_BF16(acc[mf][nf], a_hi[mf], b_lo[nf][0], b_lo[nf][1]);
                    MMA_BF16(acc[mf][nf], a_lo[mf], b_hi[nf][0], b_hi[nf][1]);
                }
        }
    };

    const int NT = K / 32;
    ldg_stage(0);
    cvt_sts(0);
    for (int t = 0; t < NT; t++) {
        if (t + 1 < NT) ldg_stage(t + 1);
        __syncthreads();
        compute(t);
        if (t + 1 < NT) cvt_sts(t + 1);
    }

#pragma unroll
    for (int mf = 0; mf < 2; mf++) {
#pragma unroll
        for (int nf = 0; nf < 4; nf++) {
            int n = bn + wn * 32 + nf * 8 + (lane & 3) * 2;
#pragma unroll
            for (int h = 0; h < 2; h++) {
                int ml = wm * 32 + mf * 16 + (lane >> 2) + h * 8;
                int m  = bm + ml;
                if (m < M) {
                    float d0 = acc[mf][nf][2 * h], d1 = acc[mf][nf][2 * h + 1];
                    if (MODE == 0) {
                        *(float2*)&g_u_shared[(size_t)m * ISD + n] = make_float2(d0, d1);
                    } else if (MODE == 1) {
                        float2 u = *(const float2*)&g_u_shared[(size_t)m * ISD + n];
                        float h0 = d0 / (1.f + expf(-d0)) * u.x;
                        float h1 = d1 / (1.f + expf(-d1)) * u.y;
                        *(float2*)&g_h_shared[(size_t)m * ISD + n] = make_float2(h0, h1);
                    } else if (MODE == 2) {
                        *(float2*)&outArg[(size_t)m * HD + n] = make_float2(d0, d1);
                    } else if (MODE == 3) {
                        *(float2*)&g_u_routed[((size_t)e * CAPN + m) * ID + n] = make_float2(d0, d1);
                    } else if (MODE == 4) {
                        float2 u = *(const float2*)&g_u_routed[((size_t)e * CAPN + m) * ID + n];
                        float h0 = d0 / (1.f + expf(-d0)) * u.x;
                        float h1 = d1 / (1.f + expf(-d1)) * u.y;
                        *(float2*)&g_h_routed[((size_t)e * CAPN + m) * ID + n] = make_float2(h0, h1);
                    } else {
                        int tok = s_tok[ml];
                        float wgt = s_wt[ml];
                        atomicAdd(&outArg[(size_t)tok * HD + n],     wgt * d0);
                        atomicAdd(&outArg[(size_t)tok * HD + n + 1], wgt * d1);
                    }
                }
            }
        }
    }
}

extern "C" void kernel_launch(void* const* d_in, const int* in_sizes, int n_in,
                              void* d_out, int out_size) {
    const float* x       = (const float*)d_in[0];
    const float* gate_w  = (const float*)d_in[1];
    const float* w_gate  = (const float*)d_in[2];
    const float* w_up    = (const float*)d_in[3];
    const float* w_down  = (const float*)d_in[4];
    const float* ws_gate = (const float*)d_in[5];
    const float* ws_up   = (const float*)d_in[6];
    const float* ws_down = (const float*)d_in[7];
    float* out = (float*)d_out;

    init_counts_kernel<<<1, 32>>>();
    router_kernel<<<TT, 512>>>(x, gate_w);

    moe_hmma<0><<<dim3(ISD / 64, TT / 64), 128, DSMEM>>>(x, ws_up, out);
    moe_hmma<1><<<dim3(ISD / 64, TT / 64), 128, DSMEM>>>(x, ws_gate, out);
    moe_hmma<2><<<dim3(HD / 64, TT / 64), 128, DSMEM>>>(x, ws_down, out);

    moe_hmma<3><<<dim3(ID / 64, CAPN / 64, ED), 128, DSMEM>>>(x, w_up, out);
    moe_hmma<4><<<dim3(ID / 64, CAPN / 64, ED), 128, DSMEM>>>(x, w_gate, out);
    moe_hmma<5><<<dim3(HD / 64, CAPN / 64, ED), 128, DSMEM>>>(x, w_down, out);
}

// round 16
// speedup vs baseline: 1.5575x; 1.1918x over previous
#include <cuda_runtime.h>
#include <cuda_bf16.h>
#include <math.h>
#include <stdint.h>

#define TT    2048
#define HD    2048
#define ID    1408
#define ED    16
#define ISD   2816
#define CAPN  1024

__device__ int   g_counts[ED];
__device__ int   g_slot_tok[ED * CAPN];
__device__ float g_slot_w[ED * CAPN];
__device__ float g_u_shared[(size_t)TT * ISD];
__device__ float g_h_shared[(size_t)TT * ISD];
__device__ float g_u_routed[(size_t)ED * CAPN * ID];
__device__ float g_h_routed[(size_t)ED * CAPN * ID];

// SMEM geometry (bytes): A tile 128 rows x 32k bf16 (stride 80B), B tile 32k x 128n bf16 (stride 272B)
#define ASTRIDE_B 80
#define BSTRIDE_B 272
#define AHI 0
#define ALO 10240
#define BHI 20480
#define BLO 29184
#define STAGE 37888
#define DSMEM (2 * STAGE)

__device__ __forceinline__ uint32_t smem_u32(const void* p) {
    uint32_t a;
    asm("{ .reg .u64 t; cvta.to.shared.u64 t, %1; cvt.u32.u64 %0, t; }" : "=r"(a) : "l"(p));
    return a;
}
__device__ __forceinline__ void sts128(uint32_t a, uint32_t x, uint32_t y, uint32_t z, uint32_t w) {
    asm volatile("st.shared.v4.b32 [%0], {%1, %2, %3, %4};" :: "r"(a), "r"(x), "r"(y), "r"(z), "r"(w) : "memory");
}
__device__ __forceinline__ void cvt_hilo(float a, float b, uint32_t& h, uint32_t& l) {
    __nv_bfloat162 hh = __floats2bfloat162_rn(a, b);
    __nv_bfloat162 ll = __floats2bfloat162_rn(a - __bfloat162float(hh.x),
                                              b - __bfloat162float(hh.y));
    h = *(uint32_t*)&hh; l = *(uint32_t*)&ll;
}

#define LDSM_X4(r, a) \
    asm volatile("ldmatrix.sync.aligned.m8n8.x4.shared.b16 {%0,%1,%2,%3}, [%4];" \
        : "=r"((r)[0]), "=r"((r)[1]), "=r"((r)[2]), "=r"((r)[3]) : "r"(a))
#define LDSM_X4T(r0, r1, r2, r3, a) \
    asm volatile("ldmatrix.sync.aligned.m8n8.x4.trans.shared.b16 {%0,%1,%2,%3}, [%4];" \
        : "=r"(r0), "=r"(r1), "=r"(r2), "=r"(r3) : "r"(a))
#define MMA_BF16(d, a, b0, b1) \
    asm volatile("mma.sync.aligned.m16n8k16.row.col.f32.bf16.bf16.f32 " \
        "{%0,%1,%2,%3}, {%4,%5,%6,%7}, {%8,%9}, {%0,%1,%2,%3};" \
        : "+f"((d)[0]), "+f"((d)[1]), "+f"((d)[2]), "+f"((d)[3]) \
        : "r"((a)[0]), "r"((a)[1]), "r"((a)[2]), "r"((a)[3]), "r"(b0), "r"(b1))

__global__ void init_counts_kernel() {
    if (threadIdx.x < ED) g_counts[threadIdx.x] = 0;
}

__global__ void router_kernel(const float* __restrict__ x, const float* __restrict__ gw) {
    int t = blockIdx.x;
    int warp = threadIdx.x >> 5, lane = threadIdx.x & 31;
    const float4* x4 = (const float4*)(x + (size_t)t * HD);
    const float4* w4 = (const float4*)(gw + (size_t)warp * HD);
    float acc = 0.f;
#pragma unroll 4
    for (int i = lane; i < HD / 4; i += 32) {
        float4 a = x4[i], b = w4[i];
        acc += a.x * b.x + a.y * b.y + a.z * b.z + a.w * b.w;
    }
#pragma unroll
    for (int o = 16; o > 0; o >>= 1) acc += __shfl_xor_sync(0xffffffffu, acc, o);
    __shared__ float logits[ED];
    if (lane == 0) logits[warp] = acc;
    __syncthreads();
    if (threadIdx.x == 0) {
        float mx = -1e30f;
        for (int e = 0; e < ED; e++) mx = fmaxf(mx, logits[e]);
        float s = 0.f, ex[ED];
        for (int e = 0; e < ED; e++) { ex[e] = expf(logits[e] - mx); s += ex[e]; }
        int i1 = 0; float v1 = logits[0];
        for (int e = 1; e < ED; e++) if (logits[e] > v1) { v1 = logits[e]; i1 = e; }
        int i2 = -1; float v2 = -1e30f;
        for (int e = 0; e < ED; e++) if (e != i1 && logits[e] > v2) { v2 = logits[e]; i2 = e; }
        float w1 = ex[i1] / s, w2 = ex[i2] / s;
        int s1 = atomicAdd(&g_counts[i1], 1);
        if (s1 < CAPN) { g_slot_tok[i1 * CAPN + s1] = t; g_slot_w[i1 * CAPN + s1] = w1; }
        int s2 = atomicAdd(&g_counts[i2], 1);
        if (s2 < CAPN) { g_slot_tok[i2 * CAPN + s2] = t; g_slot_w[i2 * CAPN + s2] = w2; }
    }
}

// modes: 0 u_sh=x@ws_up  1 h_sh=silu(x@ws_gate)*u_sh  2 out=h_sh@ws_down
//        3 u_rt=gx@w_up  4 h_rt=silu(gx@w_gate)*u_rt  5 out+=w*(h_rt@w_down)
// 256 threads, 8 warps (4m x 2n), block tile 128x128, warp tile 32m x 64n.
// __launch_bounds__(256,2): two co-resident CTAs per SM hide each other's LDG tails.
template <int MODE>
__global__ void __launch_bounds__(256, 2)
moe_hmma(const float* __restrict__ Aarg, const float* __restrict__ Barg,
         float* __restrict__ outArg)
{
    constexpr bool ROUTED = (MODE >= 3);
    constexpr bool GATHER = (MODE == 3 || MODE == 4);
    constexpr int N = (MODE <= 1) ? ISD : (MODE == 2 || MODE == 5) ? HD : ID;
    constexpr int K = (MODE <= 1) ? HD : (MODE == 2) ? ISD : (MODE == 5) ? ID : HD;

    const int e = ROUTED ? blockIdx.z : 0;
    int M;
    if (ROUTED) { M = g_counts[e]; if (M > CAPN) M = CAPN; } else M = TT;
    const int bm = blockIdx.y * 128;
    if (bm >= M) return;
    const int bn = blockIdx.x * 128;

    const int tid = threadIdx.x, lane = tid & 31, warp = tid >> 5;
    const int wm = warp & 3, wn = warp >> 2;

    __shared__ int   s_tok[128];
    __shared__ float s_wt[128];
    extern __shared__ char smem_raw[];
    const uint32_t sb = smem_u32(smem_raw);

    if (ROUTED) {
        if (tid < 128) {
            int r = bm + tid;
            s_tok[tid] = (r < M) ? g_slot_tok[e * CAPN + r] : g_slot_tok[e * CAPN];
            s_wt[tid]  = (r < M) ? g_slot_w[e * CAPN + r]  : 0.f;
        }
        __syncthreads();
    }

    const float* Abase;
    if (MODE == 2)      Abase = g_h_shared;
    else if (MODE == 5) Abase = g_h_routed + (size_t)e * CAPN * ID;
    else                Abase = Aarg;
    const float* B = Barg + (ROUTED ? (size_t)e * HD * ID : (size_t)0);

    const int arow_i = tid >> 1;
    const int kq     = (tid & 1) * 16;
    const float* arow = GATHER ? Aarg + (size_t)s_tok[arow_i] * HD
                               : Abase + (size_t)(bm + arow_i) * K;
    const int krow = tid >> 3;
    const int nq   = (tid & 7) * 16;
    const float* brow = B + (size_t)krow * N + bn + nq;

    const uint32_t a_sts = (uint32_t)(arow_i * ASTRIDE_B + kq * 2);
    const uint32_t b_sts = (uint32_t)(krow * BSTRIDE_B + nq * 2);
    const uint32_t a_ld  = (uint32_t)((wm * 32 + (lane & 15)) * ASTRIDE_B + (lane >> 4) * 16);
    const uint32_t b_ld  = (uint32_t)((lane & 15) * BSTRIDE_B + (wn * 64 + (lane >> 4) * 8) * 2);

    float acc[2][8][4];
#pragma unroll
    for (int i = 0; i < 2; i++)
#pragma unroll
        for (int j = 0; j < 8; j++)
#pragma unroll
            for (int q = 0; q < 4; q++) acc[i][j][q] = 0.f;

    // LDG + convert + STS fused at stage tail (no long-lived prefetch regs;
    // the co-resident CTA hides the LDG latency).
    auto cvt_sts = [&](int t) {
        uint32_t base = sb + (uint32_t)(t & 1) * STAGE;
        const float* pA = arow + t * 32 + kq;
        const float* pB = brow + (size_t)(t * 32) * N;
        float4 pa0 = *(const float4*)(pA);
        float4 pa1 = *(const float4*)(pA + 4);
        float4 pa2 = *(const float4*)(pA + 8);
        float4 pa3 = *(const float4*)(pA + 12);
        float4 pb0 = *(const float4*)(pB);
        float4 pb1 = *(const float4*)(pB + 4);
        float4 pb2 = *(const float4*)(pB + 8);
        float4 pb3 = *(const float4*)(pB + 12);
        uint32_t h[8], l[8];
        cvt_hilo(pa0.x, pa0.y, h[0], l[0]); cvt_hilo(pa0.z, pa0.w, h[1], l[1]);
        cvt_hilo(pa1.x, pa1.y, h[2], l[2]); cvt_hilo(pa1.z, pa1.w, h[3], l[3]);
        cvt_hilo(pa2.x, pa2.y, h[4], l[4]); cvt_hilo(pa2.z, pa2.w, h[5], l[5]);
        cvt_hilo(pa3.x, pa3.y, h[6], l[6]); cvt_hilo(pa3.z, pa3.w, h[7], l[7]);
        sts128(base + AHI + a_sts,      h[0], h[1], h[2], h[3]);
        sts128(base + AHI + a_sts + 16, h[4], h[5], h[6], h[7]);
        sts128(base + ALO + a_sts,      l[0], l[1], l[2], l[3]);
        sts128(base + ALO + a_sts + 16, l[4], l[5], l[6], l[7]);
        cvt_hilo(pb0.x, pb0.y, h[0], l[0]); cvt_hilo(pb0.z, pb0.w, h[1], l[1]);
        cvt_hilo(pb1.x, pb1.y, h[2], l[2]); cvt_hilo(pb1.z, pb1.w, h[3], l[3]);
        cvt_hilo(pb2.x, pb2.y, h[4], l[4]); cvt_hilo(pb2.z, pb2.w, h[5], l[5]);
        cvt_hilo(pb3.x, pb3.y, h[6], l[6]); cvt_hilo(pb3.z, pb3.w, h[7], l[7]);
        sts128(base + BHI + b_sts,      h[0], h[1], h[2], h[3]);
        sts128(base + BHI + b_sts + 16, h[4], h[5], h[6], h[7]);
        sts128(base + BLO + b_sts,      l[0], l[1], l[2], l[3]);
        sts128(base + BLO + b_sts + 16, l[4], l[5], l[6], l[7]);
    };

    auto compute = [&](int t) {
        uint32_t base = sb + (uint32_t)(t & 1) * STAGE;
#pragma unroll
        for (int kt = 0; kt < 2; kt++) {
            uint32_t a_hi[2][4], a_lo[2][4];
            uint32_t ab = base + AHI + a_ld + kt * 32;
            LDSM_X4(a_hi[0], ab);
            LDSM_X4(a_hi[1], ab + 16 * ASTRIDE_B);
            uint32_t al = base + ALO + a_ld + kt * 32;
            LDSM_X4(a_lo[0], al);
            LDSM_X4(a_lo[1], al + 16 * ASTRIDE_B);
            uint32_t bb = base + BHI + b_ld + kt * 16 * BSTRIDE_B;
            uint32_t bl = base + BLO + b_ld + kt * 16 * BSTRIDE_B;
#pragma unroll
            for (int nb = 0; nb < 4; nb++) {
                uint32_t bh[4], blr[4];
                LDSM_X4T(bh[0], bh[1], bh[2], bh[3], bb + nb * 32);
                LDSM_X4T(blr[0], blr[1], blr[2], blr[3], bl + nb * 32);
#pragma unroll
                for (int mf = 0; mf < 2; mf++) {
                    MMA_BF16(acc[mf][2 * nb],     a_hi[mf], bh[0],  bh[1]);
                    MMA_BF16(acc[mf][2 * nb],     a_hi[mf], blr[0], blr[1]);
                    MMA_BF16(acc[mf][2 * nb],     a_lo[mf], bh[0],  bh[1]);
                    MMA_BF16(acc[mf][2 * nb + 1], a_hi[mf], bh[2],  bh[3]);
                    MMA_BF16(acc[mf][2 * nb + 1], a_hi[mf], blr[2], blr[3]);
                    MMA_BF16(acc[mf][2 * nb + 1], a_lo[mf], bh[2],  bh[3]);
                }
            }
        }
    };

    const int NT = K / 32;
    cvt_sts(0);
    for (int t = 0; t < NT; t++) {
        __syncthreads();
        compute(t);
        if (t + 1 < NT) cvt_sts(t + 1);
    }

#pragma unroll
    for (int mf = 0; mf < 2; mf++) {
#pragma unroll
        for (int nf = 0; nf < 8; nf++) {
            int n = bn + wn * 64 + nf * 8 + (lane & 3) * 2;
#pragma unroll
            for (int h = 0; h < 2; h++) {
                int ml = wm * 32 + mf * 16 + (lane >> 2) + h * 8;
                int m  = bm + ml;
                if (m < M) {
                    float d0 = acc[mf][nf][2 * h], d1 = acc[mf][nf][2 * h + 1];
                    if (MODE == 0) {
                        *(float2*)&g_u_shared[(size_t)m * ISD + n] = make_float2(d0, d1);
                    } else if (MODE == 1) {
                        float2 u = *(const float2*)&g_u_shared[(size_t)m * ISD + n];
                        float h0 = d0 / (1.f + expf(-d0)) * u.x;
                        float h1 = d1 / (1.f + expf(-d1)) * u.y;
                        *(float2*)&g_h_shared[(size_t)m * ISD + n] = make_float2(h0, h1);
                    } else if (MODE == 2) {
                        *(float2*)&outArg[(size_t)m * HD + n] = make_float2(d0, d1);
                    } else if (MODE == 3) {
                        *(float2*)&g_u_routed[((size_t)e * CAPN + m) * ID + n] = make_float2(d0, d1);
                    } else if (MODE == 4) {
                        float2 u = *(const float2*)&g_u_routed[((size_t)e * CAPN + m) * ID + n];
                        float h0 = d0 / (1.f + expf(-d0)) * u.x;
                        float h1 = d1 / (1.f + expf(-d1)) * u.y;
                        *(float2*)&g_h_routed[((size_t)e * CAPN + m) * ID + n] = make_float2(h0, h1);
                    } else {
                        int tok = s_tok[ml];
                        float wgt = s_wt[ml];
                        atomicAdd(&outArg[(size_t)tok * HD + n],     wgt * d0);
                        atomicAdd(&outArg[(size_t)tok * HD + n + 1], wgt * d1);
                    }
                }
            }
        }
    }
}

extern "C" void kernel_launch(void* const* d_in, const int* in_sizes, int n_in,
                              void* d_out, int out_size) {
    const float* x       = (const float*)d_in[0];
    const float* gate_w  = (const float*)d_in[1];
    const float* w_gate  = (const float*)d_in[2];
    const float* w_up    = (const float*)d_in[3];
    const float* w_down  = (const float*)d_in[4];
    const float* ws_gate = (const float*)d_in[5];
    const float* ws_up   = (const float*)d_in[6];
    const float* ws_down = (const float*)d_in[7];
    float* out = (float*)d_out;

    cudaFuncSetAttribute(moe_hmma<0>, cudaFuncAttributeMaxDynamicSharedMemorySize, DSMEM);
    cudaFuncSetAttribute(moe_hmma<1>, cudaFuncAttributeMaxDynamicSharedMemorySize, DSMEM);
    cudaFuncSetAttribute(moe_hmma<2>, cudaFuncAttributeMaxDynamicSharedMemorySize, DSMEM);
    cudaFuncSetAttribute(moe_hmma<3>, cudaFuncAttributeMaxDynamicSharedMemorySize, DSMEM);
    cudaFuncSetAttribute(moe_hmma<4>, cudaFuncAttributeMaxDynamicSharedMemorySize, DSMEM);
    cudaFuncSetAttribute(moe_hmma<5>, cudaFuncAttributeMaxDynamicSharedMemorySize, DSMEM);

    init_counts_kernel<<<1, 32>>>();
    router_kernel<<<TT, 512>>>(x, gate_w);

    moe_hmma<0><<<dim3(ISD / 128, TT / 128), 256, DSMEM>>>(x, ws_up, out);
    moe_hmma<1><<<dim3(ISD / 128, TT / 128), 256, DSMEM>>>(x, ws_gate, out);
    moe_hmma<2><<<dim3(HD / 128, TT / 128), 256, DSMEM>>>(x, ws_down, out);

    moe_hmma<3><<<dim3(ID / 128, CAPN / 128, ED), 256, DSMEM>>>(x, w_up, out);
    moe_hmma<4><<<dim3(ID / 128, CAPN / 128, ED), 256, DSMEM>>>(x, w_gate, out);
    moe_hmma<5><<<dim3(HD / 128, CAPN / 128, ED), 256, DSMEM>>>(x, w_down, out);
}